// round 16
// baseline (speedup 1.0000x reference)
#include <cuda_runtime.h>
#include <cuda_fp16.h>
#include <math.h>
#include <stdint.h>

#define Bn 128
#define Tn 256
#define Ln 64
#define Sn 25
#define Hn 128
#define NT 1024

#define ZF_SZ  52428800   // 25*128*256*64
#define M_SZ   2097152    // 128*256*64

#define ZW  36    // uint32 words per z fp16 row
#define TW  68    // uint32 words per th fp16 row
#define ZFW 68    // float words per exact-z row

__device__ __forceinline__ float tanh_fast(float x) {
    float y;
    asm("tanh.approx.f32 %0, %1;" : "=f"(y) : "f"(x));
    return y;
}
__device__ __forceinline__ uint32_t pack_h2(float a, float b) {
    __half2 h = __floats2half2_rn(a, b);
    return *(uint32_t*)&h;
}
__device__ __forceinline__ void mma16816h(float* d, const uint32_t* a,
                                          uint32_t b0, uint32_t b1) {
    asm volatile(
        "mma.sync.aligned.m16n8k16.row.col.f32.f16.f16.f32 "
        "{%0,%1,%2,%3},{%4,%5,%6,%7},{%8,%9},{%0,%1,%2,%3};"
        : "+f"(d[0]), "+f"(d[1]), "+f"(d[2]), "+f"(d[3])
        : "r"(a[0]), "r"(a[1]), "r"(a[2]), "r"(a[3]), "r"(b0), "r"(b1));
}
__device__ __forceinline__ void ldm4(uint32_t addr, uint32_t* r) {
    asm volatile("ldmatrix.sync.aligned.m8n8.x4.shared.b16 {%0,%1,%2,%3}, [%4];"
        : "=r"(r[0]), "=r"(r[1]), "=r"(r[2]), "=r"(r[3]) : "r"(addr));
}

__global__ __launch_bounds__(NT, 1)
void nlf_kernel(const float* __restrict__ k_in,
                const float* __restrict__ K_in,
                const float* __restrict__ noise,
                const float* __restrict__ logQ,
                const float* __restrict__ m0,
                const float* __restrict__ logQ0,
                const float* __restrict__ W1,
                const float* __restrict__ b1,
                const float* __restrict__ W2,
                const float* __restrict__ b2,
                float* __restrict__ out)
{
    __shared__ uint32_t zH[32*ZW];     // z fp16
    __shared__ uint32_t thH[32*TW];    // tanh fp16
    __shared__ float    zf[32*ZFW];    // exact fp32 z
    __shared__ float    Pp[16*128];    // GEMM2 k-half partials
    __shared__ float    sP1[128], sP2[128];

    const int tid  = threadIdx.x;
    const int b    = blockIdx.x;
    const int w    = tid >> 5;
    const int lane = tid & 31;
    const int lq   = tid & 63;

    const int mt  = w & 1;          // m-tile (same for both GEMMs)
    const int nj1 = w >> 1;         // GEMM1 n-tile 0..15
    const int wn2 = (w >> 1) & 7;   // GEMM2 n-tile 0..7
    const int kh  = w >> 4;         // GEMM2 k-half 0/1
    const int c   = lane & 3;
    const int hq  = lane >> 2;

    const int lrow = mt*16 + (lane & 15);
    const int lcw  = (lane >> 4) * 4;
    const uint32_t zB  = (uint32_t)__cvta_generic_to_shared(zH)  + (lrow*ZW + lcw)*4;
    const uint32_t thB = (uint32_t)__cvta_generic_to_shared(thH) + (lrow*TW + lcw)*4
                         + kh*128;   // +64 halves for k-half 1

    // second z-update element: idx2 = tid + 1024 (same l as tid)
    const bool z2ok = (tid < Sn*Ln - NT);   // tid < 576
    const int  s1i  = tid >> 6;             // first element sample
    const int  s2i  = (tid + NT) >> 6;      // second element sample

    // -------- register-resident fp16 weight B-fragments --------
    uint32_t w1f[4][2];
    {
        int h = 8*nj1 + hq;
        #pragma unroll
        for (int ko = 0; ko < 4; ko++) {
            int k0 = 16*ko + 2*c;
            w1f[ko][0] = pack_h2(W1[(k0+0)*Hn + h], W1[(k0+1)*Hn + h]);
            w1f[ko][1] = pack_h2(W1[(k0+8)*Hn + h], W1[(k0+9)*Hn + h]);
        }
    }
    uint32_t w2f[4][2];
    {
        int l2 = 8*wn2 + hq;
        #pragma unroll
        for (int ko = 0; ko < 4; ko++) {
            int k0 = kh*64 + 16*ko + 2*c;
            w2f[ko][0] = pack_h2(W2[(k0+0)*Ln + l2], W2[(k0+1)*Ln + l2]);
            w2f[ko][1] = pack_h2(W2[(k0+8)*Ln + l2], W2[(k0+9)*Ln + l2]);
        }
    }
    const float b1f0 = b1[8*nj1 + 2*c];
    const float b1f1 = b1[8*nj1 + 2*c + 1];
    const float b2f0 = b2[8*wn2 + 2*c];
    const float b2f1 = b2[8*wn2 + 2*c + 1];
    const float Qd   = log1pf(expf(logQ[lq]));

    __half* zHh = (__half*)zH;      // half stride 72 per row

    // -------- init: zero fp16 arrays, t=0 filter --------
    for (int i = tid; i < 32*ZW; i += NT) zH[i] = 0;
    for (int i = tid; i < 32*TW; i += NT) thH[i] = 0;
    if (tid < 64) {
        int l = tid;
        float P0 = log1pf(expf(logQ0[l]));
        float J0 = 1.0f / P0;
        float h0 = J0 * m0[l];
        int  go  = (b*Tn + 0)*Ln + l;
        float Kv = K_in[go], kv = k_in[go];
        float Jf = J0 + Kv;
        float Pf = 1.0f / Jf;
        float mf = Pf * (h0 + kv);
        out[ZF_SZ + 0*M_SZ + go] = mf;
        out[ZF_SZ + 1*M_SZ + go] = m0[l];
        out[ZF_SZ + 2*M_SZ + go] = Pf;
        out[ZF_SZ + 3*M_SZ + go] = P0;
        sP1[l] = mf;
        sP2[l] = sqrtf(Pf);
    }
    __syncthreads();

    // z update for t = 0 (elements tid and tid+1024)
    {
        float mf = sP1[lq], spf = sP2[lq];
        {
            float zv = mf + spf * noise[((0*Sn + s1i)*Bn + b)*Ln + lq];
            out[((s1i*Bn + b)*Tn + 0)*Ln + lq] = zv;
            zf[s1i*ZFW + lq] = zv;
            zHh[s1i*72 + lq] = __float2half_rn(zv);
        }
        if (z2ok) {
            float zv = mf + spf * noise[((0*Sn + s2i)*Bn + b)*Ln + lq];
            out[((s2i*Bn + b)*Tn + 0)*Ln + lq] = zv;
            zf[s2i*ZFW + lq] = zv;
            zHh[s2i*72 + lq] = __float2half_rn(zv);
        }
    }

    const int  rowA    = mt*16 + hq;
    const bool storeHi = (mt == 0) || (hq == 0);
    const int  tile    = wn2*2 + mt;

    for (int t = 1; t < Tn; t++) {
        // -------- prefetch globals --------
        float npf0 = noise[((t*Sn + s1i)*Bn + b)*Ln + lq];
        float npf1 = z2ok ? noise[((t*Sn + s2i)*Bn + b)*Ln + lq] : 0.0f;
        const int go = (b*Tn + t)*Ln + lq;
        const float Kv_pf = K_in[go];
        const float kv_pf = k_in[go];

        __syncthreads();   // #1: z ready

        // ============ GEMM1: one m16n8 tile per warp ============
        {
            float d[4] = {b1f0, b1f1, b1f0, b1f1};
            #pragma unroll
            for (int ko = 0; ko < 4; ko++) {
                uint32_t az[4];
                ldm4(zB + 32*ko, az);
                mma16816h(d, az, w1f[ko][0], w1f[ko][1]);
            }
            int r0 = rowA*TW + 4*nj1 + c;
            thH[r0] = pack_h2(tanh_fast(d[0]), tanh_fast(d[1]));
            if (storeHi)
                thH[r0 + 8*TW] = pack_h2(tanh_fast(d[2]), tanh_fast(d[3]));
        }
        __syncthreads();   // #2: th ready

        // ============ GEMM2: m16n8, k-half per warp ============
        float e[4];
        if (kh == 0) { e[0] = b2f0; e[1] = b2f1; e[2] = b2f0; e[3] = b2f1; }
        else         { e[0] = 0.0f; e[1] = 0.0f; e[2] = 0.0f; e[3] = 0.0f; }
        #pragma unroll
        for (int ko = 0; ko < 4; ko++) {
            uint32_t at[4];
            ldm4(thB + 32*ko, at);
            mma16816h(e, at, w2f[ko][0], w2f[ko][1]);
        }
        if (kh == 1) {
            *(float2*)&Pp[tile*128 + hq*8 + 2*c]       = make_float2(e[0], e[1]);
            *(float2*)&Pp[tile*128 + (hq + 8)*8 + 2*c] = make_float2(e[2], e[3]);
        }
        __syncthreads();   // #3: partials ready

        if (kh == 0) {
            float2 p0 = *(const float2*)&Pp[tile*128 + hq*8 + 2*c];
            float2 p1 = *(const float2*)&Pp[tile*128 + (hq + 8)*8 + 2*c];
            int zb = rowA*ZFW + 8*wn2 + 2*c;
            float m0v = e[0] + p0.x + zf[zb];
            float m1v = e[1] + p0.y + zf[zb + 1];
            float m2v = e[2] + p1.x + zf[zb + 8*ZFW];
            float m3v = e[3] + p1.y + zf[zb + 8*ZFW + 1];
            if (mt == 1 && hq > 0) { m2v = 0.0f; m3v = 0.0f; }   // s >= 25
            float p0s = m0v + m2v, p1s = m1v + m3v;
            float q0s = m0v*m0v + m2v*m2v, q1s = m1v*m1v + m3v*m3v;
            #pragma unroll
            for (int msk = 4; msk <= 16; msk <<= 1) {
                p0s += __shfl_xor_sync(0xffffffffu, p0s, msk);
                p1s += __shfl_xor_sync(0xffffffffu, p1s, msk);
                q0s += __shfl_xor_sync(0xffffffffu, q0s, msk);
                q1s += __shfl_xor_sync(0xffffffffu, q1s, msk);
            }
            if ((lane & 24) == 0) {
                int li = mt*64 + 8*wn2 + 2*c;
                sP1[li] = p0s; sP1[li+1] = p1s;
                sP2[li] = q0s; sP2[li+1] = q1s;
            }
        }
        __syncthreads();   // #4: moment partials ready

        // -------- filter update (redundant per l) --------
        float s1 = sP1[lq] + sP1[64 + lq];
        float s2 = sP2[lq] + sP2[64 + lq];
        float mp = s1 * (1.0f/25.0f);
        float Ppv = Qd + s2 * (1.0f/25.0f) - mp*mp;
        float Jp = 1.0f / Ppv;
        float Jf = Jp + Kv_pf;
        float Pf = 1.0f / Jf;
        float mf = Pf * (Jp*mp + kv_pf);
        float spf = sqrtf(Pf);
        if (tid < 64) {
            out[ZF_SZ + 0*M_SZ + go] = mf;
            out[ZF_SZ + 1*M_SZ + go] = mp;
            out[ZF_SZ + 2*M_SZ + go] = Pf;
            out[ZF_SZ + 3*M_SZ + go] = Ppv;
        }

        // -------- z update + z_f output (elements tid and tid+1024) --------
        {
            float zv = mf + spf * npf0;
            out[((s1i*Bn + b)*Tn + t)*Ln + lq] = zv;
            zf[s1i*ZFW + lq] = zv;
            zHh[s1i*72 + lq] = __float2half_rn(zv);
        }
        if (z2ok) {
            float zv = mf + spf * npf1;
            out[((s2i*Bn + b)*Tn + t)*Ln + lq] = zv;
            zf[s2i*ZFW + lq] = zv;
            zHh[s2i*72 + lq] = __float2half_rn(zv);
        }
    }
}

extern "C" void kernel_launch(void* const* d_in, const int* in_sizes, int n_in,
                              void* d_out, int out_size)
{
    const float* k_in  = (const float*)d_in[0];
    const float* K_in  = (const float*)d_in[1];
    const float* noise = (const float*)d_in[2];
    const float* logQ  = (const float*)d_in[3];
    const float* m0    = (const float*)d_in[4];
    const float* logQ0 = (const float*)d_in[5];
    const float* W1    = (const float*)d_in[6];
    const float* b1    = (const float*)d_in[7];
    const float* W2    = (const float*)d_in[8];
    const float* b2    = (const float*)d_in[9];
    float* out = (float*)d_out;

    nlf_kernel<<<Bn, NT>>>(k_in, K_in, noise, logQ, m0, logQ0,
                           W1, b1, W2, b2, out);
}

// round 17
// speedup vs baseline: 1.2615x; 1.2615x over previous
#include <cuda_runtime.h>
#include <cuda_fp16.h>
#include <math.h>
#include <stdint.h>

#define Bn 128
#define Tn 256
#define Ln 64
#define Sn 25
#define Hn 128
#define NT 512

#define ZF_SZ  52428800   // 25*128*256*64
#define M_SZ   2097152    // 128*256*64

#define ZW  36    // uint32 words per z fp16 row
#define TW  68    // uint32 words per th fp16 row
#define ZFW 68    // float words per exact-z row

__device__ __forceinline__ float tanh_fast(float x) {
    float y;
    asm("tanh.approx.f32 %0, %1;" : "=f"(y) : "f"(x));
    return y;
}
__device__ __forceinline__ uint32_t pack_h2(float a, float b) {
    __half2 h = __floats2half2_rn(a, b);
    return *(uint32_t*)&h;
}
__device__ __forceinline__ void mma16816h(float* d, const uint32_t* a,
                                          uint32_t b0, uint32_t b1) {
    asm volatile(
        "mma.sync.aligned.m16n8k16.row.col.f32.f16.f16.f32 "
        "{%0,%1,%2,%3},{%4,%5,%6,%7},{%8,%9},{%0,%1,%2,%3};"
        : "+f"(d[0]), "+f"(d[1]), "+f"(d[2]), "+f"(d[3])
        : "r"(a[0]), "r"(a[1]), "r"(a[2]), "r"(a[3]), "r"(b0), "r"(b1));
}
__device__ __forceinline__ void ldm4(uint32_t addr, uint32_t* r) {
    asm volatile("ldmatrix.sync.aligned.m8n8.x4.shared.b16 {%0,%1,%2,%3}, [%4];"
        : "=r"(r[0]), "=r"(r[1]), "=r"(r[2]), "=r"(r[3]) : "r"(addr));
}

__global__ __launch_bounds__(NT, 1)
void nlf_kernel(const float* __restrict__ k_in,
                const float* __restrict__ K_in,
                const float* __restrict__ noise,
                const float* __restrict__ logQ,
                const float* __restrict__ m0,
                const float* __restrict__ logQ0,
                const float* __restrict__ W1,
                const float* __restrict__ b1,
                const float* __restrict__ W2,
                const float* __restrict__ b2,
                float* __restrict__ out)
{
    __shared__ uint32_t zH[32*ZW];     // z fp16
    __shared__ uint32_t thH[32*TW];    // tanh fp16
    __shared__ float    zf[32*ZFW];    // exact fp32 z
    __shared__ float    sP1[128], sP2[128];

    const int tid  = threadIdx.x;
    const int b    = blockIdx.x;
    const int w    = tid >> 5;
    const int lane = tid & 31;
    const int lq   = tid & 63;

    const int mt = w & 1;        // s-half m-tile
    const int wn = w >> 1;       // 0..7: GEMM1 h-pair cluster / GEMM2 l-tile
    const int c  = lane & 3;
    const int hq = lane >> 2;

    // ldmatrix per-lane addresses
    const int lrow = mt*16 + (lane & 15);
    const int lcw  = (lane >> 4) * 4;
    const uint32_t zB  = (uint32_t)__cvta_generic_to_shared(zH)  + (lrow*ZW + lcw)*4;
    const uint32_t thB = (uint32_t)__cvta_generic_to_shared(thH) + (lrow*TW + lcw)*4;

    // -------- register-resident fp16 weight B-fragments --------
    uint32_t w1f[2][4][2];
    #pragma unroll
    for (int j = 0; j < 2; j++) {
        int h = 8*(2*wn + j) + hq;
        #pragma unroll
        for (int ko = 0; ko < 4; ko++) {
            int k0 = 16*ko + 2*c;
            w1f[j][ko][0] = pack_h2(W1[(k0+0)*Hn + h], W1[(k0+1)*Hn + h]);
            w1f[j][ko][1] = pack_h2(W1[(k0+8)*Hn + h], W1[(k0+9)*Hn + h]);
        }
    }
    uint32_t w2f[8][2];
    {
        int l2 = 8*wn + hq;
        #pragma unroll
        for (int ko = 0; ko < 8; ko++) {
            int k0 = 16*ko + 2*c;
            w2f[ko][0] = pack_h2(W2[(k0+0)*Ln + l2], W2[(k0+1)*Ln + l2]);
            w2f[ko][1] = pack_h2(W2[(k0+8)*Ln + l2], W2[(k0+9)*Ln + l2]);
        }
    }
    float b1f[2][2];
    #pragma unroll
    for (int j = 0; j < 2; j++) {
        b1f[j][0] = b1[8*(2*wn + j) + 2*c];
        b1f[j][1] = b1[8*(2*wn + j) + 2*c + 1];
    }
    const float b2f0 = b2[8*wn + 2*c];
    const float b2f1 = b2[8*wn + 2*c + 1];
    const float Qd   = log1pf(expf(logQ[lq]));

    __half* zHh = (__half*)zH;     // half stride 72 per row

    // -------- init: zero fp16 arrays, t=0 filter --------
    for (int i = tid; i < 32*ZW; i += NT) zH[i] = 0;
    for (int i = tid; i < 32*TW; i += NT) thH[i] = 0;
    if (tid < 64) {
        int l = tid;
        float P0 = log1pf(expf(logQ0[l]));
        float J0 = 1.0f / P0;
        float h0 = J0 * m0[l];
        int  go  = (b*Tn + 0)*Ln + l;
        float Kv = K_in[go], kv = k_in[go];
        float Jf = J0 + Kv;
        float Pf = 1.0f / Jf;
        float mf = Pf * (h0 + kv);
        out[ZF_SZ + 0*M_SZ + go] = mf;
        out[ZF_SZ + 1*M_SZ + go] = m0[l];
        out[ZF_SZ + 2*M_SZ + go] = Pf;
        out[ZF_SZ + 3*M_SZ + go] = P0;
        sP1[l] = mf;
        sP2[l] = sqrtf(Pf);
    }
    __syncthreads();

    // z update for t = 0
    {
        float mf = sP1[lq], spf = sP2[lq];
        #pragma unroll
        for (int i = 0; i < 3; i++) {
            int idx = tid + i*NT, s = idx >> 6;
            float zv = mf + spf * noise[((0*Sn + s)*Bn + b)*Ln + lq];
            out[((s*Bn + b)*Tn + 0)*Ln + lq] = zv;
            zf[s*ZFW + lq] = zv;
            zHh[s*72 + lq] = __float2half_rn(zv);
        }
        if (tid < 64) {
            float zv = mf + spf * noise[((0*Sn + 24)*Bn + b)*Ln + lq];
            out[((24*Bn + b)*Tn + 0)*Ln + lq] = zv;
            zf[24*ZFW + lq] = zv;
            zHh[24*72 + lq] = __float2half_rn(zv);
        }
    }

    const int rowA = mt*16 + hq;
    const bool storeHi = (mt == 0) || (hq == 0);   // row rowA+8 < 25

    for (int t = 1; t < Tn; t++) {
        // -------- prefetch globals --------
        float npf[4];
        #pragma unroll
        for (int i = 0; i < 3; i++) {
            int idx = tid + i*NT;
            npf[i] = noise[((t*Sn + (idx >> 6))*Bn + b)*Ln + lq];
        }
        npf[3] = (tid < 64) ? noise[((t*Sn + 24)*Bn + b)*Ln + lq] : 0.0f;
        const int go = (b*Tn + t)*Ln + lq;
        const float Kv_pf = K_in[go];
        const float kv_pf = k_in[go];

        __syncthreads();   // #1 (full): z ready

        // ============ GEMM1: th = tanh(z @ W1 + b1), loads hoisted ============
        {
            uint32_t az[4][4];
            #pragma unroll
            for (int ko = 0; ko < 4; ko++)
                ldm4(zB + 32*ko, az[ko]);
            float d[2][4];
            #pragma unroll
            for (int j = 0; j < 2; j++) {
                d[j][0] = b1f[j][0]; d[j][1] = b1f[j][1];
                d[j][2] = b1f[j][0]; d[j][3] = b1f[j][1];
            }
            #pragma unroll
            for (int ko = 0; ko < 4; ko++) {
                mma16816h(d[0], az[ko], w1f[0][ko][0], w1f[0][ko][1]);
                mma16816h(d[1], az[ko], w1f[1][ko][0], w1f[1][ko][1]);
            }
            #pragma unroll
            for (int j = 0; j < 2; j++) {
                int nj = 2*wn + j;
                int r0 = rowA*TW + 4*nj + c;
                float t0 = tanh_fast(d[j][0]);
                float t1 = tanh_fast(d[j][1]);
                thH[r0] = pack_h2(t0, t1);
                if (storeHi) {
                    float t2 = tanh_fast(d[j][2]);
                    float t3 = tanh_fast(d[j][3]);
                    thH[r0 + 8*TW] = pack_h2(t2, t3);
                }
            }
        }
        // #2 (named, per mt-half): GEMM2 reads only its own mt's th rows,
        // which are produced exclusively by the 8 warps with the same mt.
        asm volatile("bar.sync %0, %1;" :: "r"(1 + mt), "r"(256) : "memory");

        // ============ GEMM2: m_th = z + th @ W2 + b2, pipelined loads =========
        {
            uint32_t atA[4][4], atB[4][4];
            #pragma unroll
            for (int ko = 0; ko < 4; ko++)
                ldm4(thB + 32*ko, atA[ko]);
            float e0[4] = {b2f0, b2f1, b2f0, b2f1};
            float e1[4] = {0.0f, 0.0f, 0.0f, 0.0f};
            #pragma unroll
            for (int ko = 0; ko < 4; ko++) {
                ldm4(thB + 32*(ko + 4), atB[ko]);
                mma16816h(e0, atA[ko], w2f[ko][0], w2f[ko][1]);
            }
            #pragma unroll
            for (int ko = 0; ko < 4; ko++)
                mma16816h(e1, atB[ko], w2f[ko+4][0], w2f[ko+4][1]);

            int zb = rowA*ZFW + 8*wn + 2*c;
            float m0v = e0[0] + e1[0] + zf[zb];
            float m1v = e0[1] + e1[1] + zf[zb + 1];
            float m2v = e0[2] + e1[2] + zf[zb + 8*ZFW];
            float m3v = e0[3] + e1[3] + zf[zb + 8*ZFW + 1];
            if (mt == 1 && hq > 0) { m2v = 0.0f; m3v = 0.0f; }   // rows >= 25
            float p0 = m0v + m2v, p1 = m1v + m3v;
            float q0 = m0v*m0v + m2v*m2v, q1 = m1v*m1v + m3v*m3v;
            #pragma unroll
            for (int msk = 4; msk <= 16; msk <<= 1) {
                p0 += __shfl_xor_sync(0xffffffffu, p0, msk);
                p1 += __shfl_xor_sync(0xffffffffu, p1, msk);
                q0 += __shfl_xor_sync(0xffffffffu, q0, msk);
                q1 += __shfl_xor_sync(0xffffffffu, q1, msk);
            }
            if ((lane & 24) == 0) {
                int li = mt*64 + 8*wn + 2*c;
                sP1[li] = p0; sP1[li+1] = p1;
                sP2[li] = q0; sP2[li+1] = q1;
            }
        }
        __syncthreads();   // #3 (full): moment partials ready

        // -------- filter update (all threads, redundant per l) --------
        float s1 = sP1[lq] + sP1[64 + lq];
        float s2 = sP2[lq] + sP2[64 + lq];
        float mp = s1 * (1.0f/25.0f);
        float Pp = Qd + s2 * (1.0f/25.0f) - mp*mp;
        float Jp = 1.0f / Pp;
        float Jf = Jp + Kv_pf;
        float Pf = 1.0f / Jf;
        float mf = Pf * (Jp*mp + kv_pf);
        float spf = sqrtf(Pf);
        if (tid < 64) {
            out[ZF_SZ + 0*M_SZ + go] = mf;
            out[ZF_SZ + 1*M_SZ + go] = mp;
            out[ZF_SZ + 2*M_SZ + go] = Pf;
            out[ZF_SZ + 3*M_SZ + go] = Pp;
        }

        // -------- z update + z_f output --------
        #pragma unroll
        for (int i = 0; i < 3; i++) {
            int idx = tid + i*NT, s = idx >> 6;
            float zv = mf + spf * npf[i];
            out[((s*Bn + b)*Tn + t)*Ln + lq] = zv;
            zf[s*ZFW + lq] = zv;
            zHh[s*72 + lq] = __float2half_rn(zv);
        }
        if (tid < 64) {
            float zv = mf + spf * npf[3];
            out[((24*Bn + b)*Tn + t)*Ln + lq] = zv;
            zf[24*ZFW + lq] = zv;
            zHh[24*72 + lq] = __float2half_rn(zv);
        }
    }
}

extern "C" void kernel_launch(void* const* d_in, const int* in_sizes, int n_in,
                              void* d_out, int out_size)
{
    const float* k_in  = (const float*)d_in[0];
    const float* K_in  = (const float*)d_in[1];
    const float* noise = (const float*)d_in[2];
    const float* logQ  = (const float*)d_in[3];
    const float* m0    = (const float*)d_in[4];
    const float* logQ0 = (const float*)d_in[5];
    const float* W1    = (const float*)d_in[6];
    const float* b1    = (const float*)d_in[7];
    const float* W2    = (const float*)d_in[8];
    const float* b2    = (const float*)d_in[9];
    float* out = (float*)d_out;

    nlf_kernel<<<Bn, NT>>>(k_in, K_in, noise, logQ, m0, logQ0,
                           W1, b1, W2, b2, out);
}